// round 4
// baseline (speedup 1.0000x reference)
#include <cuda_runtime.h>

#define DIM   48
#define NBINS 38

#define BIN_LO   3.25f
#define BIN_STEP (17.5f / 37.0f)    // linspace(3.25, 20.75, 38) spacing
#define BIN_INV  (37.0f / 17.5f)

__device__ __forceinline__ int bin_of(float d) {
    int k = (int)rintf((d - BIN_LO) * BIN_INV);
    k = k < 0 ? 0 : (k > NBINS - 1 ? NBINS - 1 : k);
    float best = fabsf(d - fmaf((float)k, BIN_STEP, BIN_LO));
    if (k > 0) {
        float c = fabsf(d - fmaf((float)(k - 1), BIN_STEP, BIN_LO));
        if (c < best) { best = c; k = k - 1; }
    }
    if (k < NBINS - 1) {
        float c = fabsf(d - fmaf((float)(k + 1), BIN_STEP, BIN_LO));
        if (c < best) { k = k + 1; }
    }
    return k;
}

// One warp = 2 consecutive rows. 16 lanes per row, lane 'pos' (0..11) owns one
// float4; pos 12..15 idle. Warp-level LDG/STG covers a contiguous, 384B-aligned
// 384B region -> exactly 3 cache lines per instruction (zero wavefront
// amplification). Row stats via 4-step butterfly within each 16-lane half.
// Pair rows and single-LN rows are fused into one grid (single rows are the
// tail blocks; they skip the embedding term).
__global__ __launch_bounds__(256) void fused_kernel(
    const float*  __restrict__ x,
    const float4* __restrict__ pair4,
    const float4* __restrict__ single4,
    const float4* __restrict__ W4,
    const float4* __restrict__ b4,
    const float4* __restrict__ gp4,
    const float4* __restrict__ bp4,
    const float4* __restrict__ gm4,
    const float4* __restrict__ bm4,
    float4*       __restrict__ pair_out4,
    float4*       __restrict__ single_out4,
    int L, int total, int blocksP)
{
    const int warp = threadIdx.x >> 5;
    const int lane = threadIdx.x & 31;
    const int pos  = lane & 15;          // float4 slot within row (0..11 valid)
    const int half = lane >> 4;          // which of the warp's 2 rows

    const bool is_pair = (blockIdx.x < blocksP);

    const float4* src;
    float4*       dst;
    const float4* g4;
    const float4* be4;
    int row, limit;
    if (is_pair) {
        row   = (blockIdx.x * 8 + warp) * 2 + half;
        limit = total;
        src = pair4;   dst = pair_out4;   g4 = gp4; be4 = bp4;
    } else {
        row   = ((blockIdx.x - blocksP) * 8 + warp) * 2 + half;
        limit = L;
        src = single4; dst = single_out4; g4 = gm4; be4 = bm4;
    }
    const bool live = (pos < 12) && (row < limit);

    // --- load: one float4 per live lane, warp access = 3 contiguous lines ---
    float4 v = make_float4(0.f, 0.f, 0.f, 0.f);
    if (live) v = src[row * 12 + pos];

    // --- row stats: butterfly over the 16-lane half (idle lanes add 0) ---
    float sum = v.x + v.y + v.z + v.w;
    float ssq = v.x * v.x + v.y * v.y + v.z * v.z + v.w * v.w;
    #pragma unroll
    for (int m = 1; m <= 8; m <<= 1) {
        sum += __shfl_xor_sync(0xffffffffu, sum, m);
        ssq += __shfl_xor_sync(0xffffffffu, ssq, m);
    }
    const float mu  = sum * (1.0f / DIM);
    const float var = ssq * (1.0f / DIM) - mu * mu;
    const float rs  = rsqrtf(var + 1e-5f);

    if (live) {
        const float4 G = g4[pos];
        const float4 B = be4[pos];
        float4 add = B;
        if (is_pair) {
            const int i = row / L, j = row - (row / L) * L;
            const float dx = x[3 * i]     - x[3 * j];
            const float dy = x[3 * i + 1] - x[3 * j + 1];
            const float dz = x[3 * i + 2] - x[3 * j + 2];
            const float d  = sqrtf(dx * dx + dy * dy + dz * dz + 1e-12f);
            const int kbin = bin_of(d);
            const float4 w = W4[kbin * 12 + pos];
            const float4 c = b4[pos];
            add.x += c.x + w.x;
            add.y += c.y + w.y;
            add.z += c.z + w.z;
            add.w += c.w + w.w;
        }
        float4 o;
        o.x = fmaf((v.x - mu) * rs, G.x, add.x);
        o.y = fmaf((v.y - mu) * rs, G.y, add.y);
        o.z = fmaf((v.z - mu) * rs, G.z, add.z);
        o.w = fmaf((v.w - mu) * rs, G.w, add.w);
        dst[row * 12 + pos] = o;
    }
}

// ---------------------------------------------------------------------------
extern "C" void kernel_launch(void* const* d_in, const int* in_sizes, int n_in,
                              void* d_out, int out_size) {
    const float* x      = (const float*)d_in[0];
    const float* single = (const float*)d_in[1];
    const float* pair   = (const float*)d_in[2];
    const float* W      = (const float*)d_in[3];
    const float* b      = (const float*)d_in[4];
    const float* gp     = (const float*)d_in[5];
    const float* bp     = (const float*)d_in[6];
    const float* gm     = (const float*)d_in[7];
    const float* bm     = (const float*)d_in[8];

    const int L = in_sizes[1] / DIM;            // single is [1, L, DIM]
    const int total = L * L;

    float* out        = (float*)d_out;
    float* single_out = out;                     // (single_out, pair_out) concatenated
    float* pair_out   = out + (size_t)L * DIM;

    // 16 rows per block (8 warps x 2 rows)
    const int blocksP = (total + 15) / 16;
    const int blocksS = (L + 15) / 16;

    fused_kernel<<<blocksP + blocksS, 256>>>(
        x,
        (const float4*)pair, (const float4*)single,
        (const float4*)W, (const float4*)b,
        (const float4*)gp, (const float4*)bp,
        (const float4*)gm, (const float4*)bm,
        (float4*)pair_out, (float4*)single_out,
        L, total, blocksP);
}

// round 5
// speedup vs baseline: 1.5933x; 1.5933x over previous
#include <cuda_runtime.h>

#define DIM   48
#define NBINS 38

#define BIN_LO   3.25f
#define BIN_STEP (17.5f / 37.0f)    // linspace(3.25, 20.75, 38) spacing
#define BIN_INV  (37.0f / 17.5f)

__device__ __forceinline__ int bin_of(float d) {
    int k = (int)rintf((d - BIN_LO) * BIN_INV);
    k = k < 0 ? 0 : (k > NBINS - 1 ? NBINS - 1 : k);
    float best = fabsf(d - fmaf((float)k, BIN_STEP, BIN_LO));
    if (k > 0) {
        float c = fabsf(d - fmaf((float)(k - 1), BIN_STEP, BIN_LO));
        if (c < best) { best = c; k = k - 1; }
    }
    if (k < NBINS - 1) {
        float c = fabsf(d - fmaf((float)(k + 1), BIN_STEP, BIN_LO));
        if (c < best) { k = k + 1; }
    }
    return k;
}

// 4 lanes per row (48B/thread), 2-step butterfly for row stats. Pair rows and
// single-LN rows fused into one grid (single rows = tail blocks). Epilogue is
// chunked (3 passes) to keep live registers low; streaming cache hints on the
// bulk traffic.
__global__ __launch_bounds__(256, 5) void fused_kernel(
    const float*  __restrict__ x,
    const float4* __restrict__ pair4,
    const float4* __restrict__ single4,
    const float4* __restrict__ W4,
    const float4* __restrict__ b4,
    const float4* __restrict__ gp4,
    const float4* __restrict__ bp4,
    const float4* __restrict__ gm4,
    const float4* __restrict__ bm4,
    float4*       __restrict__ pair_out4,
    float4*       __restrict__ single_out4,
    int L, int total, int blocksP, int lshift)
{
    const bool is_pair = (blockIdx.x < blocksP);

    const float4* src;
    float4*       dst;
    const float4* g4;
    const float4* be4;
    int row, limit;
    {
        int gtid;
        if (is_pair) {
            gtid  = blockIdx.x * 256 + threadIdx.x;
            limit = total;
            src = pair4;   dst = pair_out4;   g4 = gp4; be4 = bp4;
        } else {
            gtid  = (blockIdx.x - blocksP) * 256 + threadIdx.x;
            limit = L;
            src = single4; dst = single_out4; g4 = gm4; be4 = bm4;
        }
        row = gtid >> 2;
        if (row >= limit) return;
    }
    const int lane4 = threadIdx.x & 3;

    // --- load 12 elements of this row (lane-strided float4, streaming) ---
    const float4* p = src + (size_t)row * 12 + lane4;
    const float4 v0 = __ldcs(p);
    const float4 v1 = __ldcs(p + 4);
    const float4 v2 = __ldcs(p + 8);

    // --- row stats via 4-lane butterfly ---
    float sum = v0.x + v0.y + v0.z + v0.w
              + v1.x + v1.y + v1.z + v1.w
              + v2.x + v2.y + v2.z + v2.w;
    float ssq = v0.x*v0.x + v0.y*v0.y + v0.z*v0.z + v0.w*v0.w
              + v1.x*v1.x + v1.y*v1.y + v1.z*v1.z + v1.w*v1.w
              + v2.x*v2.x + v2.y*v2.y + v2.z*v2.z + v2.w*v2.w;
    sum += __shfl_xor_sync(0xffffffffu, sum, 1);
    ssq += __shfl_xor_sync(0xffffffffu, ssq, 1);
    sum += __shfl_xor_sync(0xffffffffu, sum, 2);
    ssq += __shfl_xor_sync(0xffffffffu, ssq, 2);

    const float mu  = sum * (1.0f / DIM);
    const float var = ssq * (1.0f / DIM) - mu * mu;
    const float rs  = rsqrtf(var + 1e-5f);

    float4* q = dst + (size_t)row * 12 + lane4;

    if (is_pair) {
        int i, j;
        if (lshift >= 0) { i = row >> lshift; j = row & (L - 1); }
        else             { i = row / L;       j = row - i * L;   }
        const float dx = x[3 * i]     - x[3 * j];
        const float dy = x[3 * i + 1] - x[3 * j + 1];
        const float dz = x[3 * i + 2] - x[3 * j + 2];
        const float d  = sqrtf(dx * dx + dy * dy + dz * dz + 1e-12f);
        const int kbin = bin_of(d);
        const float4* wr = W4 + kbin * 12 + lane4;

        #pragma unroll
        for (int c = 0; c < 3; c++) {
            const float4 v = (c == 0) ? v0 : (c == 1) ? v1 : v2;
            const float4 G = g4 [lane4 + 4 * c];
            const float4 B = be4[lane4 + 4 * c];
            const float4 cb = b4[lane4 + 4 * c];
            const float4 w  = wr[4 * c];
            float4 o;
            o.x = fmaf((v.x - mu) * rs, G.x, B.x + cb.x + w.x);
            o.y = fmaf((v.y - mu) * rs, G.y, B.y + cb.y + w.y);
            o.z = fmaf((v.z - mu) * rs, G.z, B.z + cb.z + w.z);
            o.w = fmaf((v.w - mu) * rs, G.w, B.w + cb.w + w.w);
            __stcs(q + 4 * c, o);
        }
    } else {
        #pragma unroll
        for (int c = 0; c < 3; c++) {
            const float4 v = (c == 0) ? v0 : (c == 1) ? v1 : v2;
            const float4 G = g4 [lane4 + 4 * c];
            const float4 B = be4[lane4 + 4 * c];
            float4 o;
            o.x = fmaf((v.x - mu) * rs, G.x, B.x);
            o.y = fmaf((v.y - mu) * rs, G.y, B.y);
            o.z = fmaf((v.z - mu) * rs, G.z, B.z);
            o.w = fmaf((v.w - mu) * rs, G.w, B.w);
            __stcs(q + 4 * c, o);
        }
    }
}

// ---------------------------------------------------------------------------
extern "C" void kernel_launch(void* const* d_in, const int* in_sizes, int n_in,
                              void* d_out, int out_size) {
    const float* x      = (const float*)d_in[0];
    const float* single = (const float*)d_in[1];
    const float* pair   = (const float*)d_in[2];
    const float* W      = (const float*)d_in[3];
    const float* b      = (const float*)d_in[4];
    const float* gp     = (const float*)d_in[5];
    const float* bp     = (const float*)d_in[6];
    const float* gm     = (const float*)d_in[7];
    const float* bm     = (const float*)d_in[8];

    const int L = in_sizes[1] / DIM;            // single is [1, L, DIM]
    const int total = L * L;

    float* out        = (float*)d_out;
    float* single_out = out;                     // (single_out, pair_out) concatenated
    float* pair_out   = out + (size_t)L * DIM;

    // power-of-two shortcut for row -> (i, j)
    int lshift = -1;
    if ((L & (L - 1)) == 0) {
        lshift = 0;
        while ((1 << lshift) < L) lshift++;
    }

    // 64 rows per block (256 threads, 4 per row)
    const int blocksP = (total + 63) / 64;
    const int blocksS = (L + 63) / 64;

    fused_kernel<<<blocksP + blocksS, 256>>>(
        x,
        (const float4*)pair, (const float4*)single,
        (const float4*)W, (const float4*)b,
        (const float4*)gp, (const float4*)bp,
        (const float4*)gm, (const float4*)bm,
        (float4*)pair_out, (float4*)single_out,
        L, total, blocksP, lshift);
}